// round 4
// baseline (speedup 1.0000x reference)
#include <cuda_runtime.h>
#include <math.h>

// ---------------- problem constants (fixed by reference) ----------------
#define NG   100
#define NPG  500
#define EPG  4000
#define NN   (NG*NPG)      // 50000 nodes
#define NE   (NG*EPG)      // 400000 edges
#define HID  128
#define H4   512
#define PQW  1024          // P (512) || Q (512)
#define KSEL 2000          // ceil(0.5 * 4000)

// output layout (float32, concatenated in reference return order)
#define O_ATT 0
#define O_CW  (NE)
#define O_SW  (2*NE)
#define O_CM  (3*NE)
#define O_EI  (4*NE)           // [2,E]: new_row then new_col
#define O_NM  (6*NE)
#define O_CX  (6*NE + NN)

// ---------------- scratch (__device__ globals; no allocation) ----------------
__device__ float         g_PQ[(size_t)NN * PQW];   // ~205 MB
__device__ unsigned char g_cmask[NE];
__device__ int           g_nm[NN];
__device__ int           g_scan[NN];
__device__ int           g_newid[NN];
__device__ int           g_bsum[128];

typedef unsigned long long u64;

// ---------------- f32x2 packed-FMA helper ----------------
__device__ __forceinline__ void fma2(u64& d, u64 a, u64 b) {
    asm("fma.rn.f32x2 %0, %1, %2, %0;" : "+l"(d) : "l"(a), "l"(b));
}
__device__ __forceinline__ void unpack2(u64 v, float& lo, float& hi) {
    asm("mov.b64 {%0,%1}, %2;" : "=f"(lo), "=f"(hi) : "l"(v));
}

// ---------------- ordered-key helpers ----------------
__device__ __forceinline__ unsigned int f2k(float f) {
    unsigned int u = __float_as_uint(f);
    return (u & 0x80000000u) ? ~u : (u | 0x80000000u);
}
__device__ __forceinline__ float k2f(unsigned int k) {
    unsigned int u = (k & 0x80000000u) ? (k & 0x7FFFFFFFu) : ~k;
    return __uint_as_float(u);
}

// ---------------- K0: zero node-mask ----------------
__global__ void k_zero_nm() {
    int n = blockIdx.x * blockDim.x + threadIdx.x;
    if (n < NN) g_nm[n] = 0;
}

// ---------------- K1: GEMM  PQ[n,0:512]=emb@W1[:128]+b1, PQ[n,512:1024]=emb@W1[128:] ----------------
// BM=BN=128, 256 thr, 8x8 microtile, zero-pack FFMA2 inner loop.
// A staged DUPLICATED [k][2m] (chunk-swizzled), B staged [k][n]; thread's 8 n-cols
// split as {tx*4..+3} and {64+tx*4..+3} for conflict-free LDS.128.
extern __shared__ float smem_dyn[];
__global__ __launch_bounds__(256, 1) void k_gemm_pq(const float* __restrict__ emb,
                                                    const float* __restrict__ W1,
                                                    const float* __restrict__ b1) {
    float* As = smem_dyn;               // [128][256] dup floats, 128KB
    float* Bs = smem_dyn + 128 * 256;   // [128][128], 64KB
    int tid   = threadIdx.x;
    int mbase = blockIdx.y * 128;
    int nbase = blockIdx.x * 128;

    // ---- load A tile: 4x4 register transpose, duplicate, chunk-swizzled store ----
    #pragma unroll
    for (int l = 0; l < 4; l++) {
        int t  = tid + l * 256;        // 0..1023
        int k4 = t & 31;               // float4 index along K
        int rb = t >> 5;               // m chunk: rows rb*4..rb*4+3 (chunk id = rb)
        float4 v[4];
        #pragma unroll
        for (int i = 0; i < 4; i++) {
            int gm = mbase + rb * 4 + i;
            v[i] = (gm < NN) ? *(const float4*)(emb + (size_t)gm * HID + k4 * 4)
                             : make_float4(0.f, 0.f, 0.f, 0.f);
        }
        const float* vv = (const float*)v;
        int s = k4 & 3;                // swizzle key (= (k>>2)&3 for k rows 4k4..4k4+3)
        int pc = (rb ^ s) * 8;         // physical chunk offset (8 dup floats)
        #pragma unroll
        for (int c = 0; c < 4; c++) {
            float a0 = vv[0*4 + c], a1 = vv[1*4 + c], a2 = vv[2*4 + c], a3 = vv[3*4 + c];
            float* dst = As + (4 * k4 + c) * 256 + pc;
            *(float4*)(dst)     = make_float4(a0, a0, a1, a1);
            *(float4*)(dst + 4) = make_float4(a2, a2, a3, a3);
        }
    }
    // ---- load B tile (direct, W1 is [k][n]) ----
    bool isQ = (nbase >= H4);
    const float* Wbase = W1 + (isQ ? (size_t)HID * H4 : 0);
    int ncol = isQ ? (nbase - H4) : nbase;
    #pragma unroll
    for (int l = 0; l < 16; l++) {
        int t  = tid + l * 256;        // 0..4095
        int kk = t >> 5;
        int n4 = t & 31;
        *(float4*)(Bs + kk * 128 + n4 * 4) =
            *(const float4*)(Wbase + (size_t)kk * H4 + ncol + n4 * 4);
    }
    __syncthreads();

    int tx = tid & 15, ty = tid >> 4;

    u64 acc[8][4];                     // [m][n-pair-group]
    #pragma unroll
    for (int m = 0; m < 8; m++)
        #pragma unroll
        for (int g = 0; g < 4; g++) acc[m][g] = 0ull;

    #pragma unroll 8
    for (int k = 0; k < 128; k++) {
        int s  = (k >> 2) & 3;
        int c0 = ((2 * ty)     ^ s) * 8;
        int c1 = ((2 * ty + 1) ^ s) * 8;
        const float* ab = As + k * 256;
        float4 A0 = *(const float4*)(ab + c0);
        float4 A1 = *(const float4*)(ab + c0 + 4);
        float4 A2 = *(const float4*)(ab + c1);
        float4 A3 = *(const float4*)(ab + c1 + 4);
        float4 B0 = *(const float4*)(Bs + k * 128 + tx * 4);
        float4 B1 = *(const float4*)(Bs + k * 128 + 64 + tx * 4);
        u64 am[8];
        am[0] = ((const u64*)&A0)[0]; am[1] = ((const u64*)&A0)[1];
        am[2] = ((const u64*)&A1)[0]; am[3] = ((const u64*)&A1)[1];
        am[4] = ((const u64*)&A2)[0]; am[5] = ((const u64*)&A2)[1];
        am[6] = ((const u64*)&A3)[0]; am[7] = ((const u64*)&A3)[1];
        u64 bp[4];
        bp[0] = ((const u64*)&B0)[0]; bp[1] = ((const u64*)&B0)[1];
        bp[2] = ((const u64*)&B1)[0]; bp[3] = ((const u64*)&B1)[1];
        #pragma unroll
        for (int m = 0; m < 8; m++)
            #pragma unroll
            for (int g = 0; g < 4; g++)
                fma2(acc[m][g], am[m], bp[g]);
    }

    // ---- epilogue: fold b1 into P half, store two float4 groups per row ----
    int n0A = nbase + tx * 4;
    int n0B = nbase + 64 + tx * 4;
    float bA[4], bB[4];
    #pragma unroll
    for (int j = 0; j < 4; j++) {
        bA[j] = (n0A + j < H4) ? b1[n0A + j] : 0.f;
        bB[j] = (n0B + j < H4) ? b1[n0B + j] : 0.f;
    }
    #pragma unroll
    for (int m = 0; m < 8; m++) {
        int gm = mbase + ty * 8 + m;
        if (gm >= NN) break;
        float a0, a1, a2, a3;
        unpack2(acc[m][0], a0, a1); unpack2(acc[m][1], a2, a3);
        *(float4*)(g_PQ + (size_t)gm * PQW + n0A) =
            make_float4(a0 + bA[0], a1 + bA[1], a2 + bA[2], a3 + bA[3]);
        unpack2(acc[m][2], a0, a1); unpack2(acc[m][3], a2, a3);
        *(float4*)(g_PQ + (size_t)gm * PQW + n0B) =
            make_float4(a0 + bB[0], a1 + bB[1], a2 + bB[2], a3 + bB[3]);
    }
}

// ---------------- K2: edge attention, one warp per edge (b1 pre-folded into P) ----------------
__global__ __launch_bounds__(256) void k_edge_att(const int* __restrict__ ei,
                                                  const float* __restrict__ W2,
                                                  const float* __restrict__ b2,
                                                  float* __restrict__ out) {
    __shared__ __align__(16) float sw2[H4];
    int tid = threadIdx.x;
    for (int i = tid; i < H4; i += blockDim.x) sw2[i] = W2[i];
    __syncthreads();

    int gw   = (blockIdx.x * blockDim.x + tid) >> 5;
    int lane = tid & 31;
    if (gw >= NE) return;
    int r = ei[gw];
    int c = ei[NE + gw];
    const float4* Pr = (const float4*)(g_PQ + (size_t)r * PQW);
    const float4* Qr = (const float4*)(g_PQ + (size_t)c * PQW + H4);
    const float4* W4 = (const float4*)sw2;

    float acc = 0.f;
    #pragma unroll
    for (int it = 0; it < 4; it++) {
        int j4 = it * 32 + lane;
        float4 p = Pr[j4];
        float4 q = Qr[j4];
        float4 ww = W4[j4];
        acc += ww.x * fmaxf(p.x + q.x, 0.f);
        acc += ww.y * fmaxf(p.y + q.y, 0.f);
        acc += ww.z * fmaxf(p.z + q.z, 0.f);
        acc += ww.w * fmaxf(p.w + q.w, 0.f);
    }
    #pragma unroll
    for (int off = 16; off > 0; off >>= 1)
        acc += __shfl_xor_sync(0xFFFFFFFFu, acc, off);
    if (lane == 0) out[O_ATT + gw] = acc + b2[0];
}

// ---------------- K3: per-graph top-k radix select (512 thr, shuffle scans) ----------------
__global__ __launch_bounds__(512) void k_select(const int* __restrict__ ei,
                                                float* __restrict__ out) {
    __shared__ unsigned int skey[EPG];     // 16KB
    __shared__ int hist[256];
    __shared__ int wtmp[16];
    __shared__ unsigned int s_prefix;
    __shared__ int s_kleft;

    int g    = blockIdx.x;
    int tid  = threadIdx.x;
    int lane = tid & 31;
    int wid  = tid >> 5;
    int base = g * EPG;

    for (int i = tid; i < EPG; i += 512) skey[i] = f2k(out[O_ATT + base + i]);
    __syncthreads();

    unsigned int prefix = 0u;
    int kleft = KSEL;
    #pragma unroll
    for (int pass = 3; pass >= 0; pass--) {
        int shift = pass * 8;
        if (tid < 256) hist[tid] = 0;
        __syncthreads();
        unsigned int maskHigh = (pass == 3) ? 0u : (0xFFFFFFFFu << (shift + 8));
        for (int i = tid; i < EPG; i += 512) {
            unsigned int k = skey[i];
            if ((k & maskHigh) == prefix)
                atomicAdd(&hist[(k >> shift) & 255], 1);
        }
        __syncthreads();
        // inclusive suffix sum over 256 buckets (warps 0..7), shuffle-based
        int myh = 0, sfx = 0;
        if (tid < 256) {
            myh = hist[tid];
            sfx = myh;
            #pragma unroll
            for (int off = 1; off < 32; off <<= 1) {
                int t = __shfl_down_sync(0xFFFFFFFFu, sfx, off);
                if (lane + off < 32) sfx += t;
            }
            if (lane == 0) wtmp[wid] = sfx;   // whole-warp total
        }
        __syncthreads();
        if (tid < 32) {
            int v = (tid < 8) ? wtmp[tid] : 0;
            #pragma unroll
            for (int off = 1; off < 8; off <<= 1) {
                int t = __shfl_down_sync(0xFFFFFFFFu, v, off);
                if (tid + off < 8) v += t;
            }
            if (tid < 8) wtmp[8 + tid] = v;   // suffix incl own warp
        }
        __syncthreads();
        if (tid < 256) {
            int incl  = sfx + ((wid < 7) ? wtmp[8 + wid + 1] : 0);  // sum buckets >= tid
            int above = incl - myh;                                  // sum buckets  > tid
            if (above < kleft && incl >= kleft) {
                s_prefix = prefix | ((unsigned int)tid << shift);
                s_kleft  = kleft - above;
            }
        }
        __syncthreads();
        prefix = s_prefix;
        kleft  = s_kleft;
    }
    __syncthreads();
    unsigned int T = prefix;   // key of the KSEL-th largest
    int need = kleft;          // how many ==T to take (first-by-index)

    // ordered prefix over equality flags (contiguous 8-elem chunks per thread)
    // NOTE: 512*8 = 4096 > EPG=4000 -> every element access MUST be guarded.
    int start = tid * 8;
    int localEq = 0;
    #pragma unroll
    for (int i = 0; i < 8; i++) {
        int idx = start + i;
        if (idx < EPG) localEq += (skey[idx] == T);
    }
    int p = localEq;
    #pragma unroll
    for (int off = 1; off < 32; off <<= 1) {
        int t = __shfl_up_sync(0xFFFFFFFFu, p, off);
        if (lane >= off) p += t;
    }
    if (lane == 31) wtmp[wid] = p;    // warp total
    __syncthreads();
    if (tid < 32) {
        int v = (tid < 16) ? wtmp[tid] : 0;
        #pragma unroll
        for (int off = 1; off < 16; off <<= 1) {
            int t = __shfl_up_sync(0xFFFFFFFFu, v, off);
            if (tid >= off) v += t;
        }
        if (tid < 16) wtmp[tid] = v;  // inclusive warp-prefix
    }
    __syncthreads();
    int run = (p - localEq) + ((wid > 0) ? wtmp[wid - 1] : 0);

    for (int i = start; i < start + 8 && i < EPG; i++) {
        unsigned int k = skey[i];
        bool causal;
        if (k > T)       causal = true;
        else if (k == T) { causal = (run < need); run++; }
        else             causal = false;
        float att = k2f(k);
        int e = base + i;
        out[O_CW + e] = causal ? att : 0.f;
        out[O_SW + e] = causal ? 0.f : att;
        out[O_CM + e] = causal ? 1.f : 0.f;
        g_cmask[e] = causal ? 1 : 0;
        if (causal) {
            g_nm[ei[e]]      = 1;   // benign races: all write 1
            g_nm[ei[NE + e]] = 1;
        }
    }
}

// ---------------- K4/K5: two-level scan of node mask ----------------
__global__ __launch_bounds__(512) void k_scan_a() {
    __shared__ int s[512];
    int tid = threadIdx.x;
    int n = blockIdx.x * 512 + tid;
    int x = (n < NN) ? g_nm[n] : 0;
    s[tid] = x;
    __syncthreads();
    for (int off = 1; off < 512; off <<= 1) {
        int v = (tid >= off) ? s[tid - off] : 0;
        __syncthreads();
        s[tid] += v;
        __syncthreads();
    }
    if (n < NN) g_scan[n] = s[tid];
    if (tid == 511) g_bsum[blockIdx.x] = s[511];
}

__global__ void k_scan_b(int nblk) {
    if (threadIdx.x == 0 && blockIdx.x == 0) {
        int running = 0;
        for (int b = 0; b < nblk; b++) {
            int t = g_bsum[b];
            g_bsum[b] = running;
            running += t;
        }
    }
}

// ---------------- K6: fused node finalize (new_id, node_mask) + causal_x copy ----------------
__global__ void k_nodes(const float* __restrict__ emb, float* __restrict__ out) {
    int i = blockIdx.x * blockDim.x + threadIdx.x;   // float4 index over [NN*32]
    if (i >= NN * 32) return;
    int node = i >> 5;
    int nmv = g_nm[node];
    float4 v = make_float4(0.f, 0.f, 0.f, 0.f);
    if (nmv) v = ((const float4*)emb)[i];
    ((float4*)(out + O_CX))[i] = v;
    if ((i & 31) == 0) {
        out[O_NM + node] = nmv ? 1.f : 0.f;
        g_newid[node] = g_scan[node] + g_bsum[node >> 9] - 1;
    }
}

// ---------------- K7: relabeled edge index ----------------
__global__ void k_edge_out(const int* __restrict__ ei, float* __restrict__ out) {
    int e = blockIdx.x * blockDim.x + threadIdx.x;
    if (e >= NE) return;
    bool c = g_cmask[e] != 0;
    int r = ei[e], cc = ei[NE + e];
    out[O_EI + e]      = c ? (float)g_newid[r]  : -1.f;
    out[O_EI + NE + e] = c ? (float)g_newid[cc] : -1.f;
}

// ---------------- launch ----------------
extern "C" void kernel_launch(void* const* d_in, const int* in_sizes, int n_in,
                              void* d_out, int out_size) {
    const float* emb = (const float*)d_in[0];
    const int*   ei  = (const int*)d_in[1];
    // d_in[2] = node_batch (implied by layout: graph = e / EPG)
    const float* W1  = (const float*)d_in[3];
    const float* b1  = (const float*)d_in[4];
    const float* W2  = (const float*)d_in[5];
    const float* b2  = (const float*)d_in[6];
    float* out = (float*)d_out;

    k_zero_nm<<<(NN + 255) / 256, 256>>>();

    const int GEMM_SMEM = (128 * 256 + 128 * 128) * 4;   // 192KB
    cudaFuncSetAttribute(k_gemm_pq, cudaFuncAttributeMaxDynamicSharedMemorySize, GEMM_SMEM);
    dim3 ggrid(PQW / 128, (NN + 127) / 128);   // (8, 391)
    k_gemm_pq<<<ggrid, 256, GEMM_SMEM>>>(emb, W1, b1);

    k_edge_att<<<(NE * 32 + 255) / 256, 256>>>(ei, W2, b2, out);

    k_select<<<NG, 512>>>(ei, out);

    int nblk = (NN + 511) / 512;            // 98
    k_scan_a<<<nblk, 512>>>();
    k_scan_b<<<1, 32>>>(nblk);

    k_nodes<<<(NN * 32 + 255) / 256, 256>>>(emb, out);
    k_edge_out<<<(NE + 255) / 256, 256>>>(ei, out);
}

// round 6
// speedup vs baseline: 1.0543x; 1.0543x over previous
#include <cuda_runtime.h>
#include <cstdint>
#include <math.h>

// ---------------- problem constants (fixed by reference) ----------------
#define NG   100
#define NPG  500
#define EPG  4000
#define NN   (NG*NPG)      // 50000 nodes
#define NE   (NG*EPG)      // 400000 edges
#define HID  128
#define H4   512
#define PQW  1024          // P (512) || Q (512)
#define KSEL 2000          // ceil(0.5 * 4000)

// output layout (float32, concatenated in reference return order)
#define O_ATT 0
#define O_CW  (NE)
#define O_SW  (2*NE)
#define O_CM  (3*NE)
#define O_EI  (4*NE)           // [2,E]: new_row then new_col
#define O_NM  (6*NE)
#define O_CX  (6*NE + NN)

// ---------------- scratch (__device__ globals; no allocation) ----------------
__device__ float         g_PQ[(size_t)NN * PQW];    // ~205 MB
__device__ float         g_ehi[(size_t)NN * HID];   // 25.6 MB
__device__ float         g_elo[(size_t)NN * HID];   // 25.6 MB
__device__ float         g_wthi[2 * H4 * HID];      // transposed W halves [half][n][k], tf32-hi
__device__ float         g_wtlo[2 * H4 * HID];      // tf32-lo
__device__ unsigned char g_cmask[NE];
__device__ int           g_nm[NN];
__device__ int           g_scan[NN];
__device__ int           g_newid[NN];
__device__ int           g_bsum[128];

// ---------------- tf32 split helper ----------------
__device__ __forceinline__ float to_tf32(float x) {
    float r;
    asm("cvt.rna.tf32.f32 %0, %1;" : "=f"(r) : "f"(x));
    return r;
}

// ---------------- ordered-key helpers ----------------
__device__ __forceinline__ unsigned int f2k(float f) {
    unsigned int u = __float_as_uint(f);
    return (u & 0x80000000u) ? ~u : (u | 0x80000000u);
}
__device__ __forceinline__ float k2f(unsigned int k) {
    unsigned int u = (k & 0x80000000u) ? (k & 0x7FFFFFFFu) : ~k;
    return __uint_as_float(u);
}

// ---------------- warp-level tf32 MMA (baseline PTX, no 'a' arch needed) ----------------
__device__ __forceinline__ void mma_tf32(float& d0, float& d1, float& d2, float& d3,
                                         uint32_t a0, uint32_t a1, uint32_t a2, uint32_t a3,
                                         uint32_t b0, uint32_t b1) {
    asm volatile(
        "mma.sync.aligned.m16n8k8.row.col.f32.tf32.tf32.f32 "
        "{%0,%1,%2,%3}, {%4,%5,%6,%7}, {%8,%9}, {%0,%1,%2,%3};"
        : "+f"(d0), "+f"(d1), "+f"(d2), "+f"(d3)
        : "r"(a0), "r"(a1), "r"(a2), "r"(a3), "r"(b0), "r"(b1));
}

// ---------------- K0: zero node-mask ----------------
__global__ void k_zero_nm() {
    int n = blockIdx.x * blockDim.x + threadIdx.x;
    if (n < NN) g_nm[n] = 0;
}

// ---------------- K-split: emb -> tf32 hi/lo ----------------
__global__ void k_split_emb(const float* __restrict__ emb) {
    int i = blockIdx.x * blockDim.x + threadIdx.x;      // float4 index over NN*HID/4
    if (i >= NN * HID / 4) return;
    float4 v = ((const float4*)emb)[i];
    float4 h, l;
    h.x = to_tf32(v.x); l.x = to_tf32(v.x - h.x);
    h.y = to_tf32(v.y); l.y = to_tf32(v.y - h.y);
    h.z = to_tf32(v.z); l.z = to_tf32(v.z - h.z);
    h.w = to_tf32(v.w); l.w = to_tf32(v.w - h.w);
    ((float4*)g_ehi)[i] = h;
    ((float4*)g_elo)[i] = l;
}

// ---------------- K-split: W1 -> transposed tf32 hi/lo  wt[half][n][k] ----------------
__global__ void k_split_w(const float* __restrict__ W1) {
    int idx = blockIdx.x * blockDim.x + threadIdx.x;    // over 256*512
    if (idx >= 2 * HID * H4) return;
    int k = idx >> 9;          // 0..255
    int n = idx & 511;
    float v = W1[idx];
    float h = to_tf32(v);
    float l = to_tf32(v - h);
    int half = k >> 7;
    int kk = k & 127;
    int d = (half * H4 + n) * HID + kk;
    g_wthi[d] = h;
    g_wtlo[d] = l;
}

// ---------------- K1: 3xTF32 GEMM via mma.sync (HMMA path) ----------------
// grid (8, 391): x = 128-wide n-tile of PQ (0..1023), y = 128-row m-tile.
// CTA 128x128, 8 warps, warp = 64x32 (4x4 m16n8 tiles), K staged 32 at a time.
// smem arrays padded to stride 36 floats -> conflict-free fragment LDS.
#define KCH   32
#define ASTR  36
#define SA_HI 0
#define SA_LO (128*ASTR)
#define SB_HI (2*128*ASTR)
#define SB_LO (3*128*ASTR)
#define GEMM_DYN (4*128*ASTR*4)   // 73728 bytes

extern __shared__ float gsm[];

__global__ __launch_bounds__(256, 1) void k_gemm_mma(const float* __restrict__ b1) {
    int tid   = threadIdx.x;
    int wid   = tid >> 5;
    int lane  = tid & 31;
    int gquad = lane >> 2;      // groupID 0..7
    int tg    = lane & 3;       // thread-in-group 0..3
    int nbase = blockIdx.x * 128;
    int mbase = blockIdx.y * 128;

    int warpM = wid & 1;        // 2 x 64 rows
    int warpN = wid >> 1;       // 4 x 32 cols

    int half   = nbase >> 9;                 // 0 = P, 1 = Q
    int nlocal = nbase & 511;
    const float* wth = g_wthi + ((size_t)half * H4 + nlocal) * HID;
    const float* wtl = g_wtlo + ((size_t)half * H4 + nlocal) * HID;

    float acc[4][4][4];
    #pragma unroll
    for (int i = 0; i < 4; i++)
        #pragma unroll
        for (int j = 0; j < 4; j++)
            #pragma unroll
            for (int r = 0; r < 4; r++) acc[i][j][r] = 0.f;

    for (int kc = 0; kc < 4; kc++) {
        // ---- stage A hi/lo and B hi/lo chunks (128 x 32 each) ----
        #pragma unroll
        for (int l = 0; l < 4; l++) {
            int t   = tid + l * 256;     // 0..1023
            int row = t >> 3;
            int q   = t & 7;
            int gm  = mbase + row;
            float4 vh = make_float4(0.f, 0.f, 0.f, 0.f), vl = vh;
            if (gm < NN) {
                vh = *(const float4*)(g_ehi + (size_t)gm * HID + kc * KCH + q * 4);
                vl = *(const float4*)(g_elo + (size_t)gm * HID + kc * KCH + q * 4);
            }
            *(float4*)(gsm + SA_HI + row * ASTR + q * 4) = vh;
            *(float4*)(gsm + SA_LO + row * ASTR + q * 4) = vl;
            *(float4*)(gsm + SB_HI + row * ASTR + q * 4) =
                *(const float4*)(wth + (size_t)row * HID + kc * KCH + q * 4);
            *(float4*)(gsm + SB_LO + row * ASTR + q * 4) =
                *(const float4*)(wtl + (size_t)row * HID + kc * KCH + q * 4);
        }
        __syncthreads();

        // ---- compute: 4 k8-steps per chunk ----
        #pragma unroll
        for (int ks = 0; ks < 4; ks++) {
            int k0 = ks * 8 + tg;
            // A fragments for 4 m-tiles (hi & lo)
            uint32_t ah[4][4], al[4][4];
            #pragma unroll
            for (int i = 0; i < 4; i++) {
                int r0 = warpM * 64 + i * 16 + gquad;
                const float* pa = gsm + r0 * ASTR + k0;
                ah[i][0] = __float_as_uint(pa[SA_HI]);
                ah[i][1] = __float_as_uint(pa[SA_HI + 8 * ASTR]);
                ah[i][2] = __float_as_uint(pa[SA_HI + 4]);
                ah[i][3] = __float_as_uint(pa[SA_HI + 8 * ASTR + 4]);
                al[i][0] = __float_as_uint(pa[SA_LO]);
                al[i][1] = __float_as_uint(pa[SA_LO + 8 * ASTR]);
                al[i][2] = __float_as_uint(pa[SA_LO + 4]);
                al[i][3] = __float_as_uint(pa[SA_LO + 8 * ASTR + 4]);
            }
            #pragma unroll
            for (int j = 0; j < 4; j++) {
                int n0 = warpN * 32 + j * 8 + gquad;
                const float* pb = gsm + n0 * ASTR + k0;
                uint32_t bh0 = __float_as_uint(pb[SB_HI]);
                uint32_t bh1 = __float_as_uint(pb[SB_HI + 4]);
                uint32_t bl0 = __float_as_uint(pb[SB_LO]);
                uint32_t bl1 = __float_as_uint(pb[SB_LO + 4]);
                #pragma unroll
                for (int i = 0; i < 4; i++) {
                    float* d = acc[i][j];
                    mma_tf32(d[0], d[1], d[2], d[3],
                             ah[i][0], ah[i][1], ah[i][2], ah[i][3], bh0, bh1);
                    mma_tf32(d[0], d[1], d[2], d[3],
                             ah[i][0], ah[i][1], ah[i][2], ah[i][3], bl0, bl1);
                    mma_tf32(d[0], d[1], d[2], d[3],
                             al[i][0], al[i][1], al[i][2], al[i][3], bh0, bh1);
                }
            }
        }
        __syncthreads();
    }

    // ---- epilogue: add b1 (P half), store float2 pairs ----
    #pragma unroll
    for (int j = 0; j < 4; j++) {
        int col = nbase + warpN * 32 + j * 8 + 2 * tg;   // even
        float2 bv = make_float2(0.f, 0.f);
        if (col < H4) bv = *(const float2*)(b1 + col);
        #pragma unroll
        for (int i = 0; i < 4; i++) {
            int row0 = mbase + warpM * 64 + i * 16 + gquad;
            float* d = acc[i][j];
            if (row0 < NN)
                *(float2*)(g_PQ + (size_t)row0 * PQW + col) =
                    make_float2(d[0] + bv.x, d[1] + bv.y);
            if (row0 + 8 < NN)
                *(float2*)(g_PQ + (size_t)(row0 + 8) * PQW + col) =
                    make_float2(d[2] + bv.x, d[3] + bv.y);
        }
    }
}

// ---------------- K2: edge attention, one warp per edge (b1 pre-folded into P) ----------------
__global__ __launch_bounds__(256) void k_edge_att(const int* __restrict__ ei,
                                                  const float* __restrict__ W2,
                                                  const float* __restrict__ b2,
                                                  float* __restrict__ out) {
    __shared__ __align__(16) float sw2[H4];
    int tid = threadIdx.x;
    for (int i = tid; i < H4; i += blockDim.x) sw2[i] = W2[i];
    __syncthreads();

    int gw   = (blockIdx.x * blockDim.x + tid) >> 5;
    int lane = tid & 31;
    if (gw >= NE) return;
    int r = ei[gw];
    int c = ei[NE + gw];
    const float4* Pr = (const float4*)(g_PQ + (size_t)r * PQW);
    const float4* Qr = (const float4*)(g_PQ + (size_t)c * PQW + H4);
    const float4* W4 = (const float4*)sw2;

    float acc = 0.f;
    #pragma unroll
    for (int it = 0; it < 4; it++) {
        int j4 = it * 32 + lane;
        float4 p = Pr[j4];
        float4 q = Qr[j4];
        float4 ww = W4[j4];
        acc += ww.x * fmaxf(p.x + q.x, 0.f);
        acc += ww.y * fmaxf(p.y + q.y, 0.f);
        acc += ww.z * fmaxf(p.z + q.z, 0.f);
        acc += ww.w * fmaxf(p.w + q.w, 0.f);
    }
    #pragma unroll
    for (int off = 16; off > 0; off >>= 1)
        acc += __shfl_xor_sync(0xFFFFFFFFu, acc, off);
    if (lane == 0) out[O_ATT + gw] = acc + b2[0];
}

// ---------------- K3: per-graph top-k radix select (512 thr, shuffle scans) ----------------
__global__ __launch_bounds__(512) void k_select(const int* __restrict__ ei,
                                                float* __restrict__ out) {
    __shared__ unsigned int skey[EPG];     // 16KB
    __shared__ int hist[256];
    __shared__ int wtmp[16];
    __shared__ unsigned int s_prefix;
    __shared__ int s_kleft;

    int g    = blockIdx.x;
    int tid  = threadIdx.x;
    int lane = tid & 31;
    int wid  = tid >> 5;
    int base = g * EPG;

    for (int i = tid; i < EPG; i += 512) skey[i] = f2k(out[O_ATT + base + i]);
    __syncthreads();

    unsigned int prefix = 0u;
    int kleft = KSEL;
    #pragma unroll
    for (int pass = 3; pass >= 0; pass--) {
        int shift = pass * 8;
        if (tid < 256) hist[tid] = 0;
        __syncthreads();
        unsigned int maskHigh = (pass == 3) ? 0u : (0xFFFFFFFFu << (shift + 8));
        for (int i = tid; i < EPG; i += 512) {
            unsigned int k = skey[i];
            if ((k & maskHigh) == prefix)
                atomicAdd(&hist[(k >> shift) & 255], 1);
        }
        __syncthreads();
        int myh = 0, sfx = 0;
        if (tid < 256) {
            myh = hist[tid];
            sfx = myh;
            #pragma unroll
            for (int off = 1; off < 32; off <<= 1) {
                int t = __shfl_down_sync(0xFFFFFFFFu, sfx, off);
                if (lane + off < 32) sfx += t;
            }
            if (lane == 0) wtmp[wid] = sfx;
        }
        __syncthreads();
        if (tid < 32) {
            int v = (tid < 8) ? wtmp[tid] : 0;
            #pragma unroll
            for (int off = 1; off < 8; off <<= 1) {
                int t = __shfl_down_sync(0xFFFFFFFFu, v, off);
                if (tid + off < 8) v += t;
            }
            if (tid < 8) wtmp[8 + tid] = v;
        }
        __syncthreads();
        if (tid < 256) {
            int incl  = sfx + ((wid < 7) ? wtmp[8 + wid + 1] : 0);
            int above = incl - myh;
            if (above < kleft && incl >= kleft) {
                s_prefix = prefix | ((unsigned int)tid << shift);
                s_kleft  = kleft - above;
            }
        }
        __syncthreads();
        prefix = s_prefix;
        kleft  = s_kleft;
    }
    __syncthreads();
    unsigned int T = prefix;
    int need = kleft;

    // ordered prefix over equality flags; 512*8=4096 > EPG=4000 -> guard everything
    int start = tid * 8;
    int localEq = 0;
    #pragma unroll
    for (int i = 0; i < 8; i++) {
        int idx = start + i;
        if (idx < EPG) localEq += (skey[idx] == T);
    }
    int p = localEq;
    #pragma unroll
    for (int off = 1; off < 32; off <<= 1) {
        int t = __shfl_up_sync(0xFFFFFFFFu, p, off);
        if (lane >= off) p += t;
    }
    if (lane == 31) wtmp[wid] = p;
    __syncthreads();
    if (tid < 32) {
        int v = (tid < 16) ? wtmp[tid] : 0;
        #pragma unroll
        for (int off = 1; off < 16; off <<= 1) {
            int t = __shfl_up_sync(0xFFFFFFFFu, v, off);
            if (tid >= off) v += t;
        }
        if (tid < 16) wtmp[tid] = v;
    }
    __syncthreads();
    int run = (p - localEq) + ((wid > 0) ? wtmp[wid - 1] : 0);

    for (int i = start; i < start + 8 && i < EPG; i++) {
        unsigned int k = skey[i];
        bool causal;
        if (k > T)       causal = true;
        else if (k == T) { causal = (run < need); run++; }
        else             causal = false;
        float att = k2f(k);
        int e = base + i;
        out[O_CW + e] = causal ? att : 0.f;
        out[O_SW + e] = causal ? 0.f : att;
        out[O_CM + e] = causal ? 1.f : 0.f;
        g_cmask[e] = causal ? 1 : 0;
        if (causal) {
            g_nm[ei[e]]      = 1;
            g_nm[ei[NE + e]] = 1;
        }
    }
}

// ---------------- K4/K5: two-level scan of node mask ----------------
__global__ __launch_bounds__(512) void k_scan_a() {
    __shared__ int s[512];
    int tid = threadIdx.x;
    int n = blockIdx.x * 512 + tid;
    int x = (n < NN) ? g_nm[n] : 0;
    s[tid] = x;
    __syncthreads();
    for (int off = 1; off < 512; off <<= 1) {
        int v = (tid >= off) ? s[tid - off] : 0;
        __syncthreads();
        s[tid] += v;
        __syncthreads();
    }
    if (n < NN) g_scan[n] = s[tid];
    if (tid == 511) g_bsum[blockIdx.x] = s[511];
}

__global__ void k_scan_b(int nblk) {
    if (threadIdx.x == 0 && blockIdx.x == 0) {
        int running = 0;
        for (int b = 0; b < nblk; b++) {
            int t = g_bsum[b];
            g_bsum[b] = running;
            running += t;
        }
    }
}

// ---------------- K6: fused node finalize (new_id, node_mask) + causal_x copy ----------------
__global__ void k_nodes(const float* __restrict__ emb, float* __restrict__ out) {
    int i = blockIdx.x * blockDim.x + threadIdx.x;
    if (i >= NN * 32) return;
    int node = i >> 5;
    int nmv = g_nm[node];
    float4 v = make_float4(0.f, 0.f, 0.f, 0.f);
    if (nmv) v = ((const float4*)emb)[i];
    ((float4*)(out + O_CX))[i] = v;
    if ((i & 31) == 0) {
        out[O_NM + node] = nmv ? 1.f : 0.f;
        g_newid[node] = g_scan[node] + g_bsum[node >> 9] - 1;
    }
}

// ---------------- K7: relabeled edge index ----------------
__global__ void k_edge_out(const int* __restrict__ ei, float* __restrict__ out) {
    int e = blockIdx.x * blockDim.x + threadIdx.x;
    if (e >= NE) return;
    bool c = g_cmask[e] != 0;
    int r = ei[e], cc = ei[NE + e];
    out[O_EI + e]      = c ? (float)g_newid[r]  : -1.f;
    out[O_EI + NE + e] = c ? (float)g_newid[cc] : -1.f;
}

// ---------------- launch ----------------
extern "C" void kernel_launch(void* const* d_in, const int* in_sizes, int n_in,
                              void* d_out, int out_size) {
    const float* emb = (const float*)d_in[0];
    const int*   ei  = (const int*)d_in[1];
    // d_in[2] = node_batch (implied by layout: graph = e / EPG)
    const float* W1  = (const float*)d_in[3];
    const float* b1  = (const float*)d_in[4];
    const float* W2  = (const float*)d_in[5];
    const float* b2  = (const float*)d_in[6];
    float* out = (float*)d_out;

    k_zero_nm<<<(NN + 255) / 256, 256>>>();
    k_split_emb<<<(NN * HID / 4 + 255) / 256, 256>>>(emb);
    k_split_w<<<(2 * HID * H4 + 255) / 256, 256>>>(W1);

    cudaFuncSetAttribute(k_gemm_mma, cudaFuncAttributeMaxDynamicSharedMemorySize, GEMM_DYN);
    dim3 ggrid(PQW / 128, (NN + 127) / 128);   // (8, 391)
    k_gemm_mma<<<ggrid, 256, GEMM_DYN>>>(b1);

    k_edge_att<<<(NE * 32 + 255) / 256, 256>>>(ei, W2, b2, out);

    k_select<<<NG, 512>>>(ei, out);

    int nblk = (NN + 511) / 512;            // 98
    k_scan_a<<<nblk, 512>>>();
    k_scan_b<<<1, 32>>>(nblk);

    k_nodes<<<(NN * 32 + 255) / 256, 256>>>(emb, out);
    k_edge_out<<<(NE + 255) / 256, 256>>>(ei, out);
}

// round 7
// speedup vs baseline: 1.0571x; 1.0027x over previous
#include <cuda_runtime.h>
#include <cstdint>
#include <math.h>

// ---------------- problem constants (fixed by reference) ----------------
#define NG   100
#define NPG  500
#define EPG  4000
#define NN   (NG*NPG)      // 50000 nodes
#define NE   (NG*EPG)      // 400000 edges
#define HID  128
#define H4   512
#define PQW  1024          // P (512) || Q (512)
#define KSEL 2000          // ceil(0.5 * 4000)

// output layout (float32, concatenated in reference return order)
#define O_ATT 0
#define O_CW  (NE)
#define O_SW  (2*NE)
#define O_CM  (3*NE)
#define O_EI  (4*NE)           // [2,E]: new_row then new_col
#define O_NM  (6*NE)
#define O_CX  (6*NE + NN)

// ---------------- scratch (__device__ globals; no allocation) ----------------
__device__ float         g_PQ[(size_t)NN * PQW];    // ~205 MB
__device__ float         g_ehi[(size_t)NN * HID];   // 25.6 MB
__device__ float         g_elo[(size_t)NN * HID];   // 25.6 MB
__device__ float         g_wthi[2 * H4 * HID];      // transposed W halves [half][n][k], tf32-hi
__device__ float         g_wtlo[2 * H4 * HID];      // tf32-lo
__device__ unsigned char g_cmask[NE];
__device__ int           g_nm[NN];
__device__ int           g_scan[NN];
__device__ int           g_newid[NN];
__device__ int           g_bsum[128];

// ---------------- tf32 split helper ----------------
__device__ __forceinline__ float to_tf32(float x) {
    float r;
    asm("cvt.rna.tf32.f32 %0, %1;" : "=f"(r) : "f"(x));
    return r;
}

// ---------------- ordered-key helpers ----------------
__device__ __forceinline__ unsigned int f2k(float f) {
    unsigned int u = __float_as_uint(f);
    return (u & 0x80000000u) ? ~u : (u | 0x80000000u);
}
__device__ __forceinline__ float k2f(unsigned int k) {
    unsigned int u = (k & 0x80000000u) ? (k & 0x7FFFFFFFu) : ~k;
    return __uint_as_float(u);
}

// ---------------- warp-level tf32 MMA (baseline PTX) ----------------
__device__ __forceinline__ void mma_tf32(float& d0, float& d1, float& d2, float& d3,
                                         uint32_t a0, uint32_t a1, uint32_t a2, uint32_t a3,
                                         uint32_t b0, uint32_t b1) {
    asm volatile(
        "mma.sync.aligned.m16n8k8.row.col.f32.tf32.tf32.f32 "
        "{%0,%1,%2,%3}, {%4,%5,%6,%7}, {%8,%9}, {%0,%1,%2,%3};"
        : "+f"(d0), "+f"(d1), "+f"(d2), "+f"(d3)
        : "r"(a0), "r"(a1), "r"(a2), "r"(a3), "r"(b0), "r"(b1));
}

// ---------------- cp.async helpers (baseline PTX, sm_80+) ----------------
__device__ __forceinline__ uint32_t smem_u32(const void* p) {
    uint32_t a;
    asm("{ .reg .u64 t; cvta.to.shared.u64 t, %1; cvt.u32.u64 %0, t; }" : "=r"(a) : "l"(p));
    return a;
}
__device__ __forceinline__ void cp16(uint32_t dst, const void* src, bool valid) {
    int sz = valid ? 16 : 0;
    asm volatile("cp.async.ca.shared.global [%0], [%1], 16, %2;"
                 :: "r"(dst), "l"(src), "r"(sz));
}
__device__ __forceinline__ void cp_commit() {
    asm volatile("cp.async.commit_group;" ::: "memory");
}
__device__ __forceinline__ void cp_wait0() {
    asm volatile("cp.async.wait_group 0;" ::: "memory");
}

// ---------------- K0: zero node-mask ----------------
__global__ void k_zero_nm() {
    int n = blockIdx.x * blockDim.x + threadIdx.x;
    if (n < NN) g_nm[n] = 0;
}

// ---------------- K-split: emb -> tf32 hi/lo ----------------
__global__ void k_split_emb(const float* __restrict__ emb) {
    int i = blockIdx.x * blockDim.x + threadIdx.x;      // float4 index over NN*HID/4
    if (i >= NN * HID / 4) return;
    float4 v = ((const float4*)emb)[i];
    float4 h, l;
    h.x = to_tf32(v.x); l.x = to_tf32(v.x - h.x);
    h.y = to_tf32(v.y); l.y = to_tf32(v.y - h.y);
    h.z = to_tf32(v.z); l.z = to_tf32(v.z - h.z);
    h.w = to_tf32(v.w); l.w = to_tf32(v.w - h.w);
    ((float4*)g_ehi)[i] = h;
    ((float4*)g_elo)[i] = l;
}

// ---------------- K-split: W1 -> transposed tf32 hi/lo  wt[half][n][k] ----------------
__global__ void k_split_w(const float* __restrict__ W1) {
    int idx = blockIdx.x * blockDim.x + threadIdx.x;    // over 256*512
    if (idx >= 2 * HID * H4) return;
    int k = idx >> 9;          // 0..255
    int n = idx & 511;
    float v = W1[idx];
    float h = to_tf32(v);
    float l = to_tf32(v - h);
    int half = k >> 7;
    int kk = k & 127;
    int d = (half * H4 + n) * HID + kk;
    g_wthi[d] = h;
    g_wtlo[d] = l;
}

// ---------------- K1: 3xTF32 GEMM via mma.sync, B-resident + cp.async A pipeline ----------------
// grid (8, 391): x = 128-wide n-tile of PQ, y = 128-row m-tile.
// CTA 128x128, 8 warps, warp = 64x32 (4x4 m16n8 tiles).
// B (128n x 128k, hi+lo) resident in smem (stride 132); A (128m x 32k) double-buffered (stride 36).
#define KCH   32
#define ASTR  36
#define BSTR  132
#define SB_HI 0
#define SB_LO (128*BSTR)               // 16896 floats
#define SA_BASE (2*128*BSTR)           // 33792 floats
#define ABUF  (128*ASTR)               // 4608 floats
#define SA_HI(b) (SA_BASE + (b)*2*ABUF)
#define SA_LO(b) (SA_HI(b) + ABUF)
#define GEMM_DYN ((SA_BASE + 4*ABUF)*4)   // 208896 bytes

extern __shared__ float gsm[];

__global__ __launch_bounds__(256, 1) void k_gemm_mma(const float* __restrict__ b1) {
    int tid   = threadIdx.x;
    int wid   = tid >> 5;
    int lane  = tid & 31;
    int gquad = lane >> 2;      // groupID 0..7
    int tg    = lane & 3;       // thread-in-group 0..3
    int nbase = blockIdx.x * 128;
    int mbase = blockIdx.y * 128;

    int warpM = wid & 1;        // 2 x 64 rows
    int warpN = wid >> 1;       // 4 x 32 cols

    int half   = nbase >> 9;                 // 0 = P, 1 = Q
    int nlocal = nbase & 511;
    const float* wth = g_wthi + ((size_t)half * H4 + nlocal) * HID;
    const float* wtl = g_wtlo + ((size_t)half * H4 + nlocal) * HID;

    uint32_t sb = smem_u32(gsm);

    // ---- prologue: stage B (hi+lo, full K) and A chunk 0 via cp.async ----
    #pragma unroll
    for (int l = 0; l < 16; l++) {
        int t   = tid + l * 256;          // 0..4095 float4s
        int row = t >> 5;                 // 0..127 (n)
        int q   = t & 31;                 // f4 within 128-float row
        cp16(sb + (SB_HI + row * BSTR + q * 4) * 4, wth + (size_t)row * HID + q * 4, true);
        cp16(sb + (SB_LO + row * BSTR + q * 4) * 4, wtl + (size_t)row * HID + q * 4, true);
    }
    #pragma unroll
    for (int l = 0; l < 4; l++) {
        int t   = tid + l * 256;          // 0..1023
        int row = t >> 3;
        int q   = t & 7;
        bool v  = (mbase + row) < NN;
        const float* sh = g_ehi + (size_t)(mbase + row) * HID + q * 4;
        const float* sl = g_elo + (size_t)(mbase + row) * HID + q * 4;
        cp16(sb + (SA_HI(0) + row * ASTR + q * 4) * 4, sh, v);
        cp16(sb + (SA_LO(0) + row * ASTR + q * 4) * 4, sl, v);
    }
    cp_commit();
    cp_wait0();
    __syncthreads();

    float acc[4][4][4];
    #pragma unroll
    for (int i = 0; i < 4; i++)
        #pragma unroll
        for (int j = 0; j < 4; j++)
            #pragma unroll
            for (int r = 0; r < 4; r++) acc[i][j][r] = 0.f;

    for (int kc = 0; kc < 4; kc++) {
        int cur = kc & 1;
        // ---- prefetch next A chunk into alternate buffer ----
        if (kc < 3) {
            int alt = cur ^ 1;
            #pragma unroll
            for (int l = 0; l < 4; l++) {
                int t   = tid + l * 256;
                int row = t >> 3;
                int q   = t & 7;
                bool v  = (mbase + row) < NN;
                const float* sh = g_ehi + (size_t)(mbase + row) * HID + (kc + 1) * KCH + q * 4;
                const float* sl = g_elo + (size_t)(mbase + row) * HID + (kc + 1) * KCH + q * 4;
                cp16(sb + (SA_HI(alt) + row * ASTR + q * 4) * 4, sh, v);
                cp16(sb + (SA_LO(alt) + row * ASTR + q * 4) * 4, sl, v);
            }
            cp_commit();
        }

        // ---- compute: 4 k8-steps on current A buffer + resident B ----
        #pragma unroll
        for (int ks = 0; ks < 4; ks++) {
            int k0 = ks * 8 + tg;                 // local k in A chunk
            int kg = kc * KCH + k0;               // global k for B
            uint32_t ah[4][4], al[4][4];
            #pragma unroll
            for (int i = 0; i < 4; i++) {
                int r0 = warpM * 64 + i * 16 + gquad;
                const float* pa = gsm + r0 * ASTR + k0;
                ah[i][0] = __float_as_uint(pa[SA_HI(cur)]);
                ah[i][1] = __float_as_uint(pa[SA_HI(cur) + 8 * ASTR]);
                ah[i][2] = __float_as_uint(pa[SA_HI(cur) + 4]);
                ah[i][3] = __float_as_uint(pa[SA_HI(cur) + 8 * ASTR + 4]);
                al[i][0] = __float_as_uint(pa[SA_LO(cur)]);
                al[i][1] = __float_as_uint(pa[SA_LO(cur) + 8 * ASTR]);
                al[i][2] = __float_as_uint(pa[SA_LO(cur) + 4]);
                al[i][3] = __float_as_uint(pa[SA_LO(cur) + 8 * ASTR + 4]);
            }
            #pragma unroll
            for (int j = 0; j < 4; j++) {
                int n0 = warpN * 32 + j * 8 + gquad;
                const float* pb = gsm + n0 * BSTR + kg;
                uint32_t bh0 = __float_as_uint(pb[SB_HI]);
                uint32_t bh1 = __float_as_uint(pb[SB_HI + 4]);
                uint32_t bl0 = __float_as_uint(pb[SB_LO]);
                uint32_t bl1 = __float_as_uint(pb[SB_LO + 4]);
                #pragma unroll
                for (int i = 0; i < 4; i++) {
                    float* d = acc[i][j];
                    mma_tf32(d[0], d[1], d[2], d[3],
                             ah[i][0], ah[i][1], ah[i][2], ah[i][3], bh0, bh1);
                    mma_tf32(d[0], d[1], d[2], d[3],
                             ah[i][0], ah[i][1], ah[i][2], ah[i][3], bl0, bl1);
                    mma_tf32(d[0], d[1], d[2], d[3],
                             al[i][0], al[i][1], al[i][2], al[i][3], bh0, bh1);
                }
            }
        }

        if (kc < 3) cp_wait0();
        __syncthreads();
    }

    // ---- epilogue: add b1 (P half), store float2 pairs ----
    #pragma unroll
    for (int j = 0; j < 4; j++) {
        int col = nbase + warpN * 32 + j * 8 + 2 * tg;   // even
        float2 bv = make_float2(0.f, 0.f);
        if (col < H4) bv = *(const float2*)(b1 + col);
        #pragma unroll
        for (int i = 0; i < 4; i++) {
            int row0 = mbase + warpM * 64 + i * 16 + gquad;
            float* d = acc[i][j];
            if (row0 < NN)
                *(float2*)(g_PQ + (size_t)row0 * PQW + col) =
                    make_float2(d[0] + bv.x, d[1] + bv.y);
            if (row0 + 8 < NN)
                *(float2*)(g_PQ + (size_t)(row0 + 8) * PQW + col) =
                    make_float2(d[2] + bv.x, d[3] + bv.y);
        }
    }
}

// ---------------- K2: edge attention, one warp per edge (b1 pre-folded into P) ----------------
__global__ __launch_bounds__(256) void k_edge_att(const int* __restrict__ ei,
                                                  const float* __restrict__ W2,
                                                  const float* __restrict__ b2,
                                                  float* __restrict__ out) {
    __shared__ __align__(16) float sw2[H4];
    int tid = threadIdx.x;
    for (int i = tid; i < H4; i += blockDim.x) sw2[i] = W2[i];
    __syncthreads();

    int gw   = (blockIdx.x * blockDim.x + tid) >> 5;
    int lane = tid & 31;
    if (gw >= NE) return;
    int r = ei[gw];
    int c = ei[NE + gw];
    const float4* Pr = (const float4*)(g_PQ + (size_t)r * PQW);
    const float4* Qr = (const float4*)(g_PQ + (size_t)c * PQW + H4);
    const float4* W4 = (const float4*)sw2;

    float acc = 0.f;
    #pragma unroll
    for (int it = 0; it < 4; it++) {
        int j4 = it * 32 + lane;
        float4 p = Pr[j4];
        float4 q = Qr[j4];
        float4 ww = W4[j4];
        acc += ww.x * fmaxf(p.x + q.x, 0.f);
        acc += ww.y * fmaxf(p.y + q.y, 0.f);
        acc += ww.z * fmaxf(p.z + q.z, 0.f);
        acc += ww.w * fmaxf(p.w + q.w, 0.f);
    }
    #pragma unroll
    for (int off = 16; off > 0; off >>= 1)
        acc += __shfl_xor_sync(0xFFFFFFFFu, acc, off);
    if (lane == 0) out[O_ATT + gw] = acc + b2[0];
}

// ---------------- K3: per-graph top-k radix select (512 thr, shuffle scans) ----------------
__global__ __launch_bounds__(512) void k_select(const int* __restrict__ ei,
                                                float* __restrict__ out) {
    __shared__ unsigned int skey[EPG];     // 16KB
    __shared__ int hist[256];
    __shared__ int wtmp[16];
    __shared__ unsigned int s_prefix;
    __shared__ int s_kleft;

    int g    = blockIdx.x;
    int tid  = threadIdx.x;
    int lane = tid & 31;
    int wid  = tid >> 5;
    int base = g * EPG;

    for (int i = tid; i < EPG; i += 512) skey[i] = f2k(out[O_ATT + base + i]);
    __syncthreads();

    unsigned int prefix = 0u;
    int kleft = KSEL;
    #pragma unroll
    for (int pass = 3; pass >= 0; pass--) {
        int shift = pass * 8;
        if (tid < 256) hist[tid] = 0;
        __syncthreads();
        unsigned int maskHigh = (pass == 3) ? 0u : (0xFFFFFFFFu << (shift + 8));
        for (int i = tid; i < EPG; i += 512) {
            unsigned int k = skey[i];
            if ((k & maskHigh) == prefix)
                atomicAdd(&hist[(k >> shift) & 255], 1);
        }
        __syncthreads();
        int myh = 0, sfx = 0;
        if (tid < 256) {
            myh = hist[tid];
            sfx = myh;
            #pragma unroll
            for (int off = 1; off < 32; off <<= 1) {
                int t = __shfl_down_sync(0xFFFFFFFFu, sfx, off);
                if (lane + off < 32) sfx += t;
            }
            if (lane == 0) wtmp[wid] = sfx;
        }
        __syncthreads();
        if (tid < 32) {
            int v = (tid < 8) ? wtmp[tid] : 0;
            #pragma unroll
            for (int off = 1; off < 8; off <<= 1) {
                int t = __shfl_down_sync(0xFFFFFFFFu, v, off);
                if (tid + off < 8) v += t;
            }
            if (tid < 8) wtmp[8 + tid] = v;
        }
        __syncthreads();
        if (tid < 256) {
            int incl  = sfx + ((wid < 7) ? wtmp[8 + wid + 1] : 0);
            int above = incl - myh;
            if (above < kleft && incl >= kleft) {
                s_prefix = prefix | ((unsigned int)tid << shift);
                s_kleft  = kleft - above;
            }
        }
        __syncthreads();
        prefix = s_prefix;
        kleft  = s_kleft;
    }
    __syncthreads();
    unsigned int T = prefix;
    int need = kleft;

    // ordered prefix over equality flags; 512*8=4096 > EPG=4000 -> guard everything
    int start = tid * 8;
    int localEq = 0;
    #pragma unroll
    for (int i = 0; i < 8; i++) {
        int idx = start + i;
        if (idx < EPG) localEq += (skey[idx] == T);
    }
    int p = localEq;
    #pragma unroll
    for (int off = 1; off < 32; off <<= 1) {
        int t = __shfl_up_sync(0xFFFFFFFFu, p, off);
        if (lane >= off) p += t;
    }
    if (lane == 31) wtmp[wid] = p;
    __syncthreads();
    if (tid < 32) {
        int v = (tid < 16) ? wtmp[tid] : 0;
        #pragma unroll
        for (int off = 1; off < 16; off <<= 1) {
            int t = __shfl_up_sync(0xFFFFFFFFu, v, off);
            if (tid >= off) v += t;
        }
        if (tid < 16) wtmp[tid] = v;
    }
    __syncthreads();
    int run = (p - localEq) + ((wid > 0) ? wtmp[wid - 1] : 0);

    for (int i = start; i < start + 8 && i < EPG; i++) {
        unsigned int k = skey[i];
        bool causal;
        if (k > T)       causal = true;
        else if (k == T) { causal = (run < need); run++; }
        else             causal = false;
        float att = k2f(k);
        int e = base + i;
        out[O_CW + e] = causal ? att : 0.f;
        out[O_SW + e] = causal ? 0.f : att;
        out[O_CM + e] = causal ? 1.f : 0.f;
        g_cmask[e] = causal ? 1 : 0;
        if (causal) {
            g_nm[ei[e]]      = 1;
            g_nm[ei[NE + e]] = 1;
        }
    }
}

// ---------------- K4/K5: two-level scan of node mask ----------------
__global__ __launch_bounds__(512) void k_scan_a() {
    __shared__ int s[512];
    int tid = threadIdx.x;
    int n = blockIdx.x * 512 + tid;
    int x = (n < NN) ? g_nm[n] : 0;
    s[tid] = x;
    __syncthreads();
    for (int off = 1; off < 512; off <<= 1) {
        int v = (tid >= off) ? s[tid - off] : 0;
        __syncthreads();
        s[tid] += v;
        __syncthreads();
    }
    if (n < NN) g_scan[n] = s[tid];
    if (tid == 511) g_bsum[blockIdx.x] = s[511];
}

__global__ void k_scan_b(int nblk) {
    if (threadIdx.x == 0 && blockIdx.x == 0) {
        int running = 0;
        for (int b = 0; b < nblk; b++) {
            int t = g_bsum[b];
            g_bsum[b] = running;
            running += t;
        }
    }
}

// ---------------- K6: fused node finalize (new_id, node_mask) + causal_x copy ----------------
__global__ void k_nodes(const float* __restrict__ emb, float* __restrict__ out) {
    int i = blockIdx.x * blockDim.x + threadIdx.x;
    if (i >= NN * 32) return;
    int node = i >> 5;
    int nmv = g_nm[node];
    float4 v = make_float4(0.f, 0.f, 0.f, 0.f);
    if (nmv) v = ((const float4*)emb)[i];
    ((float4*)(out + O_CX))[i] = v;
    if ((i & 31) == 0) {
        out[O_NM + node] = nmv ? 1.f : 0.f;
        g_newid[node] = g_scan[node] + g_bsum[node >> 9] - 1;
    }
}

// ---------------- K7: relabeled edge index ----------------
__global__ void k_edge_out(const int* __restrict__ ei, float* __restrict__ out) {
    int e = blockIdx.x * blockDim.x + threadIdx.x;
    if (e >= NE) return;
    bool c = g_cmask[e] != 0;
    int r = ei[e], cc = ei[NE + e];
    out[O_EI + e]      = c ? (float)g_newid[r]  : -1.f;
    out[O_EI + NE + e] = c ? (float)g_newid[cc] : -1.f;
}

// ---------------- launch ----------------
extern "C" void kernel_launch(void* const* d_in, const int* in_sizes, int n_in,
                              void* d_out, int out_size) {
    const float* emb = (const float*)d_in[0];
    const int*   ei  = (const int*)d_in[1];
    // d_in[2] = node_batch (implied by layout: graph = e / EPG)
    const float* W1  = (const float*)d_in[3];
    const float* b1  = (const float*)d_in[4];
    const float* W2  = (const float*)d_in[5];
    const float* b2  = (const float*)d_in[6];
    float* out = (float*)d_out;

    k_zero_nm<<<(NN + 255) / 256, 256>>>();
    k_split_emb<<<(NN * HID / 4 + 255) / 256, 256>>>(emb);
    k_split_w<<<(2 * HID * H4 + 255) / 256, 256>>>(W1);

    cudaFuncSetAttribute(k_gemm_mma, cudaFuncAttributeMaxDynamicSharedMemorySize, GEMM_DYN);
    dim3 ggrid(PQW / 128, (NN + 127) / 128);   // (8, 391)
    k_gemm_mma<<<ggrid, 256, GEMM_DYN>>>(b1);

    k_edge_att<<<(NE * 32 + 255) / 256, 256>>>(ei, W2, b2, out);

    k_select<<<NG, 512>>>(ei, out);

    int nblk = (NN + 511) / 512;            // 98
    k_scan_a<<<nblk, 512>>>();
    k_scan_b<<<1, 32>>>(nblk);

    k_nodes<<<(NN * 32 + 255) / 256, 256>>>(emb, out);
    k_edge_out<<<(NE + 255) / 256, 256>>>(ei, out);
}